// round 7
// baseline (speedup 1.0000x reference)
#include <cuda_runtime.h>
#include <cstdint>

// out[n,64] = sum over edges e with dst[e]==n of x[src[e],:] * w[e]
// Inputs: x (float32, N*64), edge_index ((2,E), int64-or-int32), edge_weight (float32, E)

static constexpr int D       = 64;   // feature dim
static constexpr int TPB     = 256;  // threads per block
static constexpr int BATCH   = 256;  // edges staged per block
static constexpr int GROUPS  = TPB / 16;       // 16 edge-groups per pass
static constexpr int PASSES  = BATCH / GROUPS; // 16 serial edges per thread
static constexpr int UNROLL  = 8;    // gathers in flight per thread (full path)

// Probe result: 1 if edge_index is stored as int64, 0 if int32.
__device__ int g_idx_is64;

// Fused: zero the output AND (block 0 only) probe the index dtype.
// int64 indices < 2^31 => every odd 32-bit word is zero; int32 indices are
// random node ids, so all-zero over 1024 samples has probability ~1e-5024.
__global__ void zero_and_probe_kernel(float4* __restrict__ out, int n4,
                                      const int* __restrict__ ei32, int E) {
    if (blockIdx.x == 0) {
        __shared__ int any_nonzero;
        if (threadIdx.x == 0) any_nonzero = 0;
        __syncthreads();
        int n = E < 1024 ? E : 1024;
        for (int i = threadIdx.x; i < n; i += blockDim.x)
            if (ei32[2 * i + 1] != 0) any_nonzero = 1;
        __syncthreads();
        if (threadIdx.x == 0) g_idx_is64 = (any_nonzero == 0) ? 1 : 0;
    }
    int i = blockIdx.x * blockDim.x + threadIdx.x;
    if (i < n4) out[i] = make_float4(0.f, 0.f, 0.f, 0.f);
}

__device__ __forceinline__ void red_v4(float* p, float4 m) {
    asm volatile("red.global.add.v4.f32 [%0], {%1, %2, %3, %4};"
                 :: "l"(p), "f"(m.x), "f"(m.y), "f"(m.z), "f"(m.w)
                 : "memory");
}

__global__ __launch_bounds__(TPB)
void mp_scatter_batched_kernel(const float* __restrict__ x,
                               const void* __restrict__ edge_index,
                               const float* __restrict__ w,
                               float* __restrict__ out,
                               int E) {
    // One 16B record per edge: {src, dst, w_bits, pad} -> single LDS.128 read.
    __shared__ int4 s_edge[BATCH];

    const int t     = threadIdx.x;
    const int lane  = t & 15;   // which float4 of the 64-dim row
    const int group = t >> 4;   // which edge within a pass

    const int base = blockIdx.x * BATCH;
    const int n = (E - base < BATCH) ? (E - base) : BATCH;

    // ---- Stage batch of edges into smem (coalesced; int64 -> int32) ----
    if (t < n) {
        int s, d;
        if (g_idx_is64) {
            const long long* p = (const long long*)edge_index;
            s = (int)__ldg(p + base + t);
            d = (int)__ldg(p + E + base + t);
        } else {
            const int* p = (const int*)edge_index;
            s = __ldg(p + base + t);
            d = __ldg(p + E + base + t);
        }
        float wv = __ldg(w + base + t);
        s_edge[t] = make_int4(s, d, __float_as_int(wv), 0);
    }
    __syncthreads();

    if (n == BATCH) {
        // ---- Fast path: full batch, branch-free, 8 gathers in flight ----
        #pragma unroll
        for (int p = 0; p < PASSES; p += UNROLL) {
            int    dsts[UNROLL];
            float  wts [UNROLL];
            float4 xv  [UNROLL];

            #pragma unroll
            for (int u = 0; u < UNROLL; u++) {
                int i = group + GROUPS * (p + u);
                int4 er = s_edge[i];                 // one LDS.128
                unsigned s = (unsigned)er.x;
                dsts[u] = er.y;
                wts [u] = __int_as_float(er.z);
                xv[u] = __ldg(reinterpret_cast<const float4*>(x + s * D) + lane);
            }
            #pragma unroll
            for (int u = 0; u < UNROLL; u++) {
                float wt = wts[u];
                float4 m;
                m.x = xv[u].x * wt; m.y = xv[u].y * wt;
                m.z = xv[u].z * wt; m.w = xv[u].w * wt;
                red_v4(out + (unsigned)dsts[u] * D + lane * 4, m);
            }
        }
    } else {
        // ---- Tail path: guarded (at most one block) ----
        for (int p = 0; p < PASSES; p += 4) {
            int    eidx[4];
            int    dsts[4];
            float  wts [4];
            float4 xv  [4];
            #pragma unroll
            for (int u = 0; u < 4; u++) {
                int i = group + GROUPS * (p + u);
                eidx[u] = i;
                bool ok = (i < n);
                int4 er = ok ? s_edge[i] : make_int4(0, 0, 0, 0);
                unsigned s = (unsigned)er.x;
                dsts[u] = er.y;
                wts [u] = __int_as_float(er.z);
                xv[u] = __ldg(reinterpret_cast<const float4*>(x + s * D) + lane);
            }
            #pragma unroll
            for (int u = 0; u < 4; u++) {
                if (eidx[u] < n) {
                    float wt = wts[u];
                    float4 m;
                    m.x = xv[u].x * wt; m.y = xv[u].y * wt;
                    m.z = xv[u].z * wt; m.w = xv[u].w * wt;
                    red_v4(out + (unsigned)dsts[u] * D + lane * 4, m);
                }
            }
        }
    }
}

extern "C" void kernel_launch(void* const* d_in, const int* in_sizes, int n_in,
                              void* d_out, int out_size) {
    const float* x   = (const float*)d_in[0];
    const void*  ei  = d_in[1];
    const float* w   = (const float*)d_in[2];
    float*       out = (float*)d_out;

    const int E = in_sizes[1] / 2;   // edge_index is (2, E)

    // 1) zero output (poisoned 0xAA) + probe index dtype (block 0)
    {
        int n4 = out_size / 4;
        int blocks = (n4 + TPB - 1) / TPB;
        zero_and_probe_kernel<<<blocks, TPB>>>((float4*)out, n4,
                                               (const int*)ei, E);
    }

    // 2) batched gather-multiply-scatter
    {
        int blocks = (E + BATCH - 1) / BATCH;
        mp_scatter_batched_kernel<<<blocks, TPB>>>(x, ei, w, out, E);
    }
}

// round 8
// speedup vs baseline: 1.0166x; 1.0166x over previous
#include <cuda_runtime.h>
#include <cstdint>

// out[n,64] = sum over edges e with dst[e]==n of x[src[e],:] * w[e]
// Inputs: x (float32, N*64), edge_index ((2,E), int64-or-int32), edge_weight (float32, E)
//
// Strategy: bucketed CSR-lite. Build per-dst buckets of {src,w} records
// (atomicAdd on small int counters only), then an atomic-free gather pass
// writes each output row exactly once with plain stores. This removes the
// 307MB red.global.v4.f32 stream that capped rounds 5-7 at ~57us.

static constexpr int D    = 64;       // feature dim
static constexpr int TPB  = 256;
static constexpr int MAXN = 100352;   // >= N (problem: 100000)
static constexpr int CAP  = 32;       // bucket capacity per node (P(deg>32)~4e-6 total)

// ---- device scratch (static globals: the sanctioned no-alloc scratch) ----
__device__ int g_idx_is64;
__device__ int g_overflow;                       // any edge took the fallback path?
__device__ int g_count[MAXN];                    // per-node degree counters
__device__ unsigned long long g_bucket[(size_t)MAXN * CAP];  // {src, w} records

__device__ __forceinline__ void red_v4(float* p, float4 m) {
    asm volatile("red.global.add.v4.f32 [%0], {%1, %2, %3, %4};"
                 :: "l"(p), "f"(m.x), "f"(m.y), "f"(m.z), "f"(m.w)
                 : "memory");
}

// ---- 1) init: zero out + counters + overflow flag, probe index dtype ----
// int64 indices < 2^31 => every odd 32-bit word is zero; int32 indices are
// random node ids, so all-zero over 1024 samples has probability ~1e-5024.
__global__ void init_kernel(float4* __restrict__ out, int n4,
                            const int* __restrict__ ei32, int E, int N) {
    int i = blockIdx.x * blockDim.x + threadIdx.x;
    if (blockIdx.x == 0) {
        __shared__ int any_nonzero;
        if (threadIdx.x == 0) any_nonzero = 0;
        __syncthreads();
        int n = E < 1024 ? E : 1024;
        for (int k = threadIdx.x; k < n; k += blockDim.x)
            if (ei32[2 * k + 1] != 0) any_nonzero = 1;
        __syncthreads();
        if (threadIdx.x == 0) {
            g_idx_is64 = (any_nonzero == 0) ? 1 : 0;
            g_overflow = 0;
        }
    }
    if (i < n4) out[i] = make_float4(0.f, 0.f, 0.f, 0.f);
    if (i < N)  g_count[i] = 0;
}

// ---- 2) fill: bucket every edge by dst ----
__global__ __launch_bounds__(TPB)
void fill_kernel(const float* __restrict__ x,
                 const void* __restrict__ edge_index,
                 const float* __restrict__ w,
                 float* __restrict__ out,
                 int E) {
    int e = blockIdx.x * blockDim.x + threadIdx.x;
    if (e >= E) return;

    int s, d;
    if (g_idx_is64) {
        const long long* p = (const long long*)edge_index;
        s = (int)__ldg(p + e);
        d = (int)__ldg(p + E + e);
    } else {
        const int* p = (const int*)edge_index;
        s = __ldg(p + e);
        d = __ldg(p + E + e);
    }
    float wt = __ldg(w + e);

    int slot = atomicAdd(&g_count[d], 1);
    if (slot < CAP) {
        unsigned long long rec = (unsigned long long)(unsigned)s
                               | ((unsigned long long)__float_as_uint(wt) << 32);
        g_bucket[(size_t)d * CAP + slot] = rec;
    } else {
        // Overflow fallback (expected ~never): direct atomic reduction.
        g_overflow = 1;
        const float4* xr = reinterpret_cast<const float4*>(x + (size_t)(unsigned)s * D);
        float* orow = out + (size_t)(unsigned)d * D;
        #pragma unroll
        for (int l = 0; l < D / 4; l++) {
            float4 v = __ldg(xr + l);
            float4 m;
            m.x = v.x * wt; m.y = v.y * wt; m.z = v.z * wt; m.w = v.w * wt;
            red_v4(orow + l * 4, m);
        }
    }
}

// ---- 3) gather: 16 threads per node, atomic-free, one STG.128 per lane ----
__global__ __launch_bounds__(TPB)
void gather_kernel(const float* __restrict__ x,
                   float* __restrict__ out,
                   int N) {
    int gid  = blockIdx.x * blockDim.x + threadIdx.x;
    int node = gid >> 4;
    int lane = gid & 15;
    if (node >= N) return;

    int deg = g_count[node];
    if (deg > CAP) deg = CAP;
    const unsigned long long* buf = g_bucket + (size_t)node * CAP;

    float4 a0 = make_float4(0.f, 0.f, 0.f, 0.f);
    float4 a1 = make_float4(0.f, 0.f, 0.f, 0.f);
    float4 a2 = make_float4(0.f, 0.f, 0.f, 0.f);
    float4 a3 = make_float4(0.f, 0.f, 0.f, 0.f);

    int i = 0;
    for (; i + 4 <= deg; i += 4) {
        unsigned long long r0 = buf[i + 0];
        unsigned long long r1 = buf[i + 1];
        unsigned long long r2 = buf[i + 2];
        unsigned long long r3 = buf[i + 3];
        // 4 independent row gathers in flight
        float4 v0 = __ldg(reinterpret_cast<const float4*>(x + (size_t)(unsigned)(r0 & 0xffffffffu) * D) + lane);
        float4 v1 = __ldg(reinterpret_cast<const float4*>(x + (size_t)(unsigned)(r1 & 0xffffffffu) * D) + lane);
        float4 v2 = __ldg(reinterpret_cast<const float4*>(x + (size_t)(unsigned)(r2 & 0xffffffffu) * D) + lane);
        float4 v3 = __ldg(reinterpret_cast<const float4*>(x + (size_t)(unsigned)(r3 & 0xffffffffu) * D) + lane);
        float w0 = __uint_as_float((unsigned)(r0 >> 32));
        float w1 = __uint_as_float((unsigned)(r1 >> 32));
        float w2 = __uint_as_float((unsigned)(r2 >> 32));
        float w3 = __uint_as_float((unsigned)(r3 >> 32));
        a0.x += v0.x * w0; a0.y += v0.y * w0; a0.z += v0.z * w0; a0.w += v0.w * w0;
        a1.x += v1.x * w1; a1.y += v1.y * w1; a1.z += v1.z * w1; a1.w += v1.w * w1;
        a2.x += v2.x * w2; a2.y += v2.y * w2; a2.z += v2.z * w2; a2.w += v2.w * w2;
        a3.x += v3.x * w3; a3.y += v3.y * w3; a3.z += v3.z * w3; a3.w += v3.w * w3;
    }
    for (; i < deg; i++) {
        unsigned long long r = buf[i];
        float4 v = __ldg(reinterpret_cast<const float4*>(x + (size_t)(unsigned)(r & 0xffffffffu) * D) + lane);
        float wt = __uint_as_float((unsigned)(r >> 32));
        a0.x += v.x * wt; a0.y += v.y * wt; a0.z += v.z * wt; a0.w += v.w * wt;
    }

    float4 r;
    r.x = (a0.x + a1.x) + (a2.x + a3.x);
    r.y = (a0.y + a1.y) + (a2.y + a3.y);
    r.z = (a0.z + a1.z) + (a2.z + a3.z);
    r.w = (a0.w + a1.w) + (a2.w + a3.w);

    float4* orow = reinterpret_cast<float4*>(out + (size_t)node * D) + lane;
    if (g_overflow) {   // uniform branch; ~never taken
        float4 ov = *orow;  // contributions RED'd by the fallback path
        r.x += ov.x; r.y += ov.y; r.z += ov.z; r.w += ov.w;
    }
    *orow = r;
}

extern "C" void kernel_launch(void* const* d_in, const int* in_sizes, int n_in,
                              void* d_out, int out_size) {
    const float* x   = (const float*)d_in[0];
    const void*  ei  = d_in[1];
    const float* w   = (const float*)d_in[2];
    float*       out = (float*)d_out;

    const int E = in_sizes[1] / 2;       // edge_index is (2, E)
    const int N = out_size / D;          // number of nodes

    // 1) init: zero out + counters, probe dtype
    {
        int n4 = out_size / 4;
        int span = n4 > N ? n4 : N;
        int blocks = (span + TPB - 1) / TPB;
        init_kernel<<<blocks, TPB>>>((float4*)out, n4, (const int*)ei, E, N);
    }
    // 2) bucket edges by dst
    {
        int blocks = (E + TPB - 1) / TPB;
        fill_kernel<<<blocks, TPB>>>(x, ei, w, out, E);
    }
    // 3) atomic-free gather/accumulate/store
    {
        long long total = (long long)N * 16;
        int blocks = (int)((total + TPB - 1) / TPB);
        gather_kernel<<<blocks, TPB>>>(x, out, N);
    }
}

// round 9
// speedup vs baseline: 1.0625x; 1.0452x over previous
#include <cuda_runtime.h>
#include <cstdint>

// out[n,64] = sum over edges e with dst[e]==n of x[src[e],:] * w[e]
// Inputs: x (float32, N*64), edge_index ((2,E), int64-or-int32), edge_weight (float32, E)
//
// Bucketed CSR-lite, zero-free:
//   init : zero per-node counters (400KB) + probe index dtype
//   fill : bucket each edge by dst ({src,w} 8B record); overflow -> list
//   gather: 16 threads/node, atomic-free accumulate, plain STG per row
//   fixup: RED-add overflow-list edges (normally empty)
// No output zeroing: gather writes every row unconditionally.

static constexpr int D    = 64;       // feature dim
static constexpr int TPB  = 256;
static constexpr int MAXN = 100352;   // >= N (problem: 100000)
static constexpr int CAP  = 32;       // bucket slots/node (P(deg>32) ~ 4e-6 overall)
static constexpr int OVFC = 1250000;  // overflow capacity >= E (worst case)

// ---- device scratch (static globals: sanctioned no-alloc scratch) ----
__device__ int g_idx_is64;
__device__ int g_ovf_tail;
__device__ int g_count[MAXN];                                 // per-node counters
__device__ unsigned long long g_bucket[(size_t)MAXN * CAP];   // {src, w} records
__device__ unsigned long long g_ovf_rec[OVFC];                // overflow {src, w}
__device__ int g_ovf_dst[OVFC];                               // overflow dst

__device__ __forceinline__ void red_v4(float* p, float4 m) {
    asm volatile("red.global.add.v4.f32 [%0], {%1, %2, %3, %4};"
                 :: "l"(p), "f"(m.x), "f"(m.y), "f"(m.z), "f"(m.w)
                 : "memory");
}

// ---- 1) init: zero counters + overflow tail, probe index dtype ----
// int64 indices < 2^31 => every odd 32-bit word is zero; int32 indices are
// random node ids, so all-zero over 1024 samples has probability ~1e-5024.
__global__ void init_kernel(const int* __restrict__ ei32, int E, int N) {
    int i = blockIdx.x * blockDim.x + threadIdx.x;
    if (blockIdx.x == 0) {
        __shared__ int any_nonzero;
        if (threadIdx.x == 0) any_nonzero = 0;
        __syncthreads();
        int n = E < 1024 ? E : 1024;
        for (int k = threadIdx.x; k < n; k += blockDim.x)
            if (ei32[2 * k + 1] != 0) any_nonzero = 1;
        __syncthreads();
        if (threadIdx.x == 0) {
            g_idx_is64 = (any_nonzero == 0) ? 1 : 0;
            g_ovf_tail = 0;
        }
    }
    if (i < N) g_count[i] = 0;
}

// ---- 2) fill: bucket every edge by dst ----
__global__ __launch_bounds__(TPB)
void fill_kernel(const void* __restrict__ edge_index,
                 const float* __restrict__ w,
                 int E) {
    int e = blockIdx.x * blockDim.x + threadIdx.x;
    if (e >= E) return;

    int s, d;
    if (g_idx_is64) {
        const long long* p = (const long long*)edge_index;
        s = (int)__ldg(p + e);
        d = (int)__ldg(p + E + e);
    } else {
        const int* p = (const int*)edge_index;
        s = __ldg(p + e);
        d = __ldg(p + E + e);
    }
    float wt = __ldg(w + e);

    unsigned long long rec = (unsigned long long)(unsigned)s
                           | ((unsigned long long)__float_as_uint(wt) << 32);
    int slot = atomicAdd(&g_count[d], 1);
    if (slot < CAP) {
        g_bucket[(size_t)d * CAP + slot] = rec;
    } else {
        // Overflow (expected ~never): append to list, applied post-gather.
        int idx = atomicAdd(&g_ovf_tail, 1);
        if (idx < OVFC) {           // OVFC >= E, so always true; guard anyway
            g_ovf_rec[idx] = rec;
            g_ovf_dst[idx] = d;
        }
    }
}

// ---- 3) gather: 16 threads/node, atomic-free, one STG.128 per lane ----
__global__ __launch_bounds__(TPB)
void gather_kernel(const float* __restrict__ x,
                   float* __restrict__ out,
                   int N) {
    int gid  = blockIdx.x * blockDim.x + threadIdx.x;
    int node = gid >> 4;
    int lane = gid & 15;
    if (node >= N) return;

    int deg = g_count[node];
    if (deg > CAP) deg = CAP;
    const unsigned long long* buf = g_bucket + (size_t)node * CAP;

    float4 a0 = make_float4(0.f, 0.f, 0.f, 0.f);
    float4 a1 = make_float4(0.f, 0.f, 0.f, 0.f);
    float4 a2 = make_float4(0.f, 0.f, 0.f, 0.f);
    float4 a3 = make_float4(0.f, 0.f, 0.f, 0.f);

    int i = 0;
    for (; i + 4 <= deg; i += 4) {
        unsigned long long r0 = buf[i + 0];
        unsigned long long r1 = buf[i + 1];
        unsigned long long r2 = buf[i + 2];
        unsigned long long r3 = buf[i + 3];
        // 4 independent row gathers in flight
        float4 v0 = __ldg(reinterpret_cast<const float4*>(x + (size_t)(unsigned)(r0 & 0xffffffffu) * D) + lane);
        float4 v1 = __ldg(reinterpret_cast<const float4*>(x + (size_t)(unsigned)(r1 & 0xffffffffu) * D) + lane);
        float4 v2 = __ldg(reinterpret_cast<const float4*>(x + (size_t)(unsigned)(r2 & 0xffffffffu) * D) + lane);
        float4 v3 = __ldg(reinterpret_cast<const float4*>(x + (size_t)(unsigned)(r3 & 0xffffffffu) * D) + lane);
        float w0 = __uint_as_float((unsigned)(r0 >> 32));
        float w1 = __uint_as_float((unsigned)(r1 >> 32));
        float w2 = __uint_as_float((unsigned)(r2 >> 32));
        float w3 = __uint_as_float((unsigned)(r3 >> 32));
        a0.x += v0.x * w0; a0.y += v0.y * w0; a0.z += v0.z * w0; a0.w += v0.w * w0;
        a1.x += v1.x * w1; a1.y += v1.y * w1; a1.z += v1.z * w1; a1.w += v1.w * w1;
        a2.x += v2.x * w2; a2.y += v2.y * w2; a2.z += v2.z * w2; a2.w += v2.w * w2;
        a3.x += v3.x * w3; a3.y += v3.y * w3; a3.z += v3.z * w3; a3.w += v3.w * w3;
    }
    for (; i < deg; i++) {
        unsigned long long r = buf[i];
        float4 v = __ldg(reinterpret_cast<const float4*>(x + (size_t)(unsigned)(r & 0xffffffffu) * D) + lane);
        float wt = __uint_as_float((unsigned)(r >> 32));
        a0.x += v.x * wt; a0.y += v.y * wt; a0.z += v.z * wt; a0.w += v.w * wt;
    }

    float4 r;
    r.x = (a0.x + a1.x) + (a2.x + a3.x);
    r.y = (a0.y + a1.y) + (a2.y + a3.y);
    r.z = (a0.z + a1.z) + (a2.z + a3.z);
    r.w = (a0.w + a1.w) + (a2.w + a3.w);

    *(reinterpret_cast<float4*>(out + (size_t)node * D) + lane) = r;
}

// ---- 4) fixup: apply overflow-list edges (normally zero work) ----
__global__ __launch_bounds__(TPB)
void fixup_kernel(const float* __restrict__ x,
                  float* __restrict__ out) {
    int tail = g_ovf_tail;
    if (tail > OVFC) tail = OVFC;
    for (int e = blockIdx.x * blockDim.x + threadIdx.x; e < tail;
         e += gridDim.x * blockDim.x) {
        unsigned long long rec = g_ovf_rec[e];
        int d = g_ovf_dst[e];
        unsigned s = (unsigned)(rec & 0xffffffffu);
        float wt = __uint_as_float((unsigned)(rec >> 32));
        const float4* xr = reinterpret_cast<const float4*>(x + (size_t)s * D);
        float* orow = out + (size_t)d * D;
        #pragma unroll
        for (int l = 0; l < D / 4; l++) {
            float4 v = __ldg(xr + l);
            float4 m;
            m.x = v.x * wt; m.y = v.y * wt; m.z = v.z * wt; m.w = v.w * wt;
            red_v4(orow + l * 4, m);
        }
    }
}

extern "C" void kernel_launch(void* const* d_in, const int* in_sizes, int n_in,
                              void* d_out, int out_size) {
    const float* x   = (const float*)d_in[0];
    const void*  ei  = d_in[1];
    const float* w   = (const float*)d_in[2];
    float*       out = (float*)d_out;

    const int E = in_sizes[1] / 2;       // edge_index is (2, E)
    const int N = out_size / D;          // number of nodes

    // 1) init: zero counters, probe dtype (no output zeroing needed)
    {
        int blocks = (N + TPB - 1) / TPB;
        init_kernel<<<blocks, TPB>>>((const int*)ei, E, N);
    }
    // 2) bucket edges by dst
    {
        int blocks = (E + TPB - 1) / TPB;
        fill_kernel<<<blocks, TPB>>>(ei, w, E);
    }
    // 3) atomic-free gather/accumulate/store (writes every row)
    {
        long long total = (long long)N * 16;
        int blocks = (int)((total + TPB - 1) / TPB);
        gather_kernel<<<blocks, TPB>>>(x, out, N);
    }
    // 4) overflow fixup (normally empty)
    fixup_kernel<<<64, TPB>>>(x, out);
}